// round 16
// baseline (speedup 1.0000x reference)
#include <cuda_runtime.h>
#include <math.h>

// Problem shape (fixed by setup_inputs): B=8, Sq=Sk=1024, D=64, N_QUBITS=4.
#define B_     8
#define SQ_    1024
#define SK_    1024
#define D_     64
#define NQ_    4

// ---------------------------------------------------------------------------
// packed f32x2 helpers
// ---------------------------------------------------------------------------
__device__ __forceinline__ unsigned long long f2fma(unsigned long long a,
                                                    unsigned long long b,
                                                    unsigned long long c)
{
    unsigned long long d;
    asm("fma.rn.f32x2 %0, %1, %2, %3;" : "=l"(d) : "l"(a), "l"(b), "l"(c));
    return d;
}
__device__ __forceinline__ unsigned long long f2mul(unsigned long long a,
                                                    unsigned long long b)
{
    unsigned long long d;
    asm("mul.rn.f32x2 %0, %1, %2;" : "=l"(d) : "l"(a), "l"(b));
    return d;
}
__device__ __forceinline__ unsigned long long f2dup(float v)
{
    unsigned long long d;
    asm("mov.b64 %0, {%1, %1};" : "=l"(d) : "f"(v));
    return d;
}

#define HALF2_ 0x3F0000003F000000ULL   // {0.5f, 0.5f}
#define PI_    3.14159265358979323846f

// fast tanh: 1 - 2/(e^{2x}+1).  MUFU ex2 + rcp; saturates correctly at +-1.
__device__ __forceinline__ float fast_tanh(float x)
{
    float e = __expf(2.0f * x);
    return 1.0f - __fdividef(2.0f, e + 1.0f);
}

// Bloch-rotation columns of M = Rz(om)*Ry(th)*Rz(phi):  u = M*ex, v = M*ez
__device__ __forceinline__ void uv_cols(float phi, float th, float om,
                                        float u[3], float v[3])
{
    float sp, cp, st, ct, so, co;
    __sincosf(phi, &sp, &cp);
    __sincosf(th,  &st, &ct);
    __sincosf(om,  &so, &co);
    float ax = ct * cp, ay = sp, az = -st * cp;
    u[0] = ax * co - ay * so;
    u[1] = ax * so + ay * co;
    u[2] = az;
    v[0] = st * co;
    v[1] = st * so;
    v[2] = ct;
}

// per-row trig: t = tanh(x), (S,C) = sincos(pi t)
__device__ __forceinline__ void row_sc(float4 xv, float S[NQ_], float C[NQ_])
{
    float xs[4] = {xv.x, xv.y, xv.z, xv.w};
#pragma unroll
    for (int n = 0; n < NQ_; n++) {
        float t = fast_tanh(xs[n]);
        __sincosf(t * PI_, &S[n], &C[n]);
    }
}

// ---------------------------------------------------------------------------
// FUSED kernel, single __syncthreads, 256q x 256k tile, 512 threads.
// Grid = 4 x 4 x 8 = 128 blocks -> strictly one wave, one block per SM.
//   out[b][q][k] = 0.5 + 0.5 * prod_n (0.5 + q.(G_n k))
// prep: tid<256 -> q row tid ; tid>=256 -> raw k col tid-256 (perfect split);
//       tid<16 also computes the 16 Gram entries.
// main: thread owns 4 k-cols (k4 = tid&63) as packed f32x2 pairs (G folded
//       once in regs), iterates 32 q-rows (qg = tid>>6) jammed 2 at a time.
// ---------------------------------------------------------------------------
#define TQ 256
#define TK 256

__global__ __launch_bounds__(512, 1) void fused_kernel(
    float* __restrict__ out,
    const float* __restrict__ query,
    const float* __restrict__ key,
    const float* __restrict__ theta_q,
    const float* __restrict__ theta_k)
{
    __shared__ __align__(16) float  sq[TQ][8];         // 0.5*(S,C) q rows
    __shared__ __align__(16) float4 skv[8][TK / 4];    // SoA RAW k tile
    __shared__ __align__(8)  float2 sGd[16];           // {g,g} duplicated

    int b  = blockIdx.z;
    int q0 = blockIdx.y * TQ;
    int k0 = blockIdx.x * TK;
    int tid = threadIdx.x;

    // ---- issue row LDG first (overlaps the Gram chain) ----
    bool isQ = tid < TQ;
    int r = isQ ? (b * SQ_ + q0 + tid) : (b * SK_ + k0 + (tid - TQ));
    float4 xv = *(const float4*)((isQ ? query : key) + (size_t)r * D_);

    // ---- Gram entries (threads 0..15, redundant per block) ----
    if (tid < 16) {
        int n = tid >> 2, i = (tid >> 1) & 1, j = tid & 1;
        float uq[3], vq[3], uk[3], vk[3];
        uv_cols(theta_q[3 * n], theta_q[3 * n + 1], theta_q[3 * n + 2], uq, vq);
        uv_cols(theta_k[3 * n], theta_k[3 * n + 1], theta_k[3 * n + 2], uk, vk);
        const float* a  = i ? vq : uq;
        const float* bb = j ? vk : uk;
        float g = a[0] * bb[0] + a[1] * bb[1] + a[2] * bb[2];
        sGd[tid] = make_float2(g, g);
    }

    // ---- per-row (S,C) ----
    {
        float S[NQ_], C[NQ_];
        row_sc(xv, S, C);
        if (isQ) {
            float out8[8];
#pragma unroll
            for (int n = 0; n < NQ_; n++) {
                out8[2 * n]     = 0.5f * S[n];
                out8[2 * n + 1] = 0.5f * C[n];
            }
            *(float4*)&sq[tid][0] = *(const float4*)(out8);
            *(float4*)&sq[tid][4] = *(const float4*)(out8 + 4);
        } else {
            int s = tid - TQ;      // raw k col (no G yet)
            float* skf = (float*)skv;   // [comp][TK] floats
#pragma unroll
            for (int n = 0; n < NQ_; n++) {
                skf[(2 * n)     * TK + s] = S[n];
                skf[(2 * n + 1) * TK + s] = C[n];
            }
        }
    }
    __syncthreads();           // sGd + both tiles ready (single barrier)

    int k4 = tid & 63;     // this thread's 4 consecutive k columns
    int qg = tid >> 6;     // q group: rows qg*32 .. qg*32+31 (warp-uniform)

    // raw k tile -> registers, fold G once (16 packed ops, one-time)
    ulonglong2 kd[8];
#pragma unroll
    for (int j = 0; j < 8; j++)
        kd[j] = *(const ulonglong2*)&skv[j][k4];

#pragma unroll
    for (int n = 0; n < NQ_; n++) {
        unsigned long long g00 = *(const unsigned long long*)&sGd[n * 4 + 0];
        unsigned long long g01 = *(const unsigned long long*)&sGd[n * 4 + 1];
        unsigned long long g10 = *(const unsigned long long*)&sGd[n * 4 + 2];
        unsigned long long g11 = *(const unsigned long long*)&sGd[n * 4 + 3];
        ulonglong2 Sv = kd[2 * n], Cv = kd[2 * n + 1];
        kd[2 * n].x     = f2fma(g00, Sv.x, f2mul(g01, Cv.x));
        kd[2 * n].y     = f2fma(g00, Sv.y, f2mul(g01, Cv.y));
        kd[2 * n + 1].x = f2fma(g10, Sv.x, f2mul(g11, Cv.x));
        kd[2 * n + 1].y = f2fma(g10, Sv.y, f2mul(g11, Cv.y));
    }

    float* obase = out + ((size_t)(b * SQ_ + q0 + qg * 32) * SK_) + k0 + k4 * 4;

#pragma unroll
    for (int rr = 0; rr < 16; rr++) {
        int ra = qg * 32 + 2 * rr;

        // two rows' q vectors (4 warp-uniform LDS.128)
        float4 a0 = *(const float4*)&sq[ra][0];
        float4 a1 = *(const float4*)&sq[ra][4];
        float4 b0 = *(const float4*)&sq[ra + 1][0];
        float4 b1 = *(const float4*)&sq[ra + 1][4];

        unsigned long long qa[8], qb[8];
        qa[0] = f2dup(a0.x); qa[1] = f2dup(a0.y);
        qa[2] = f2dup(a0.z); qa[3] = f2dup(a0.w);
        qa[4] = f2dup(a1.x); qa[5] = f2dup(a1.y);
        qa[6] = f2dup(a1.z); qa[7] = f2dup(a1.w);
        qb[0] = f2dup(b0.x); qb[1] = f2dup(b0.y);
        qb[2] = f2dup(b0.z); qb[3] = f2dup(b0.w);
        qb[4] = f2dup(b1.x); qb[5] = f2dup(b1.y);
        qb[6] = f2dup(b1.z); qb[7] = f2dup(b1.w);

        unsigned long long ta0[NQ_], ta1[NQ_], tb0[NQ_], tb1[NQ_];
#pragma unroll
        for (int n = 0; n < NQ_; n++) {
            ta0[n] = f2fma(qa[2 * n], kd[2 * n].x,
                     f2fma(qa[2 * n + 1], kd[2 * n + 1].x, HALF2_));
            ta1[n] = f2fma(qa[2 * n], kd[2 * n].y,
                     f2fma(qa[2 * n + 1], kd[2 * n + 1].y, HALF2_));
            tb0[n] = f2fma(qb[2 * n], kd[2 * n].x,
                     f2fma(qb[2 * n + 1], kd[2 * n + 1].x, HALF2_));
            tb1[n] = f2fma(qb[2 * n], kd[2 * n].y,
                     f2fma(qb[2 * n + 1], kd[2 * n + 1].y, HALF2_));
        }
        unsigned long long pa0 = f2mul(f2mul(ta0[0], ta0[1]), f2mul(ta0[2], ta0[3]));
        unsigned long long pa1 = f2mul(f2mul(ta1[0], ta1[1]), f2mul(ta1[2], ta1[3]));
        unsigned long long pb0 = f2mul(f2mul(tb0[0], tb0[1]), f2mul(tb0[2], tb0[3]));
        unsigned long long pb1 = f2mul(f2mul(tb1[0], tb1[1]), f2mul(tb1[2], tb1[3]));
        pa0 = f2fma(pa0, HALF2_, HALF2_);
        pa1 = f2fma(pa1, HALF2_, HALF2_);
        pb0 = f2fma(pb0, HALF2_, HALF2_);
        pb1 = f2fma(pb1, HALF2_, HALF2_);

        float* oa = obase + (size_t)(2 * rr) * SK_;
        asm volatile("st.global.v2.b64 [%0], {%1, %2};"
                     :: "l"(oa), "l"(pa0), "l"(pa1) : "memory");
        asm volatile("st.global.v2.b64 [%0], {%1, %2};"
                     :: "l"(oa + SK_), "l"(pb0), "l"(pb1) : "memory");
    }
}

extern "C" void kernel_launch(void* const* d_in, const int* in_sizes, int n_in,
                              void* d_out, int out_size)
{
    const float* query   = (const float*)d_in[0];
    const float* key     = (const float*)d_in[1];
    const float* theta_q = (const float*)d_in[2];
    const float* theta_k = (const float*)d_in[3];
    float* out = (float*)d_out;

    dim3 grid(SK_ / TK, SQ_ / TQ, B_);
    fused_kernel<<<grid, 512>>>(out, query, key, theta_q, theta_k);
}

// round 17
// speedup vs baseline: 1.2557x; 1.2557x over previous
#include <cuda_runtime.h>
#include <math.h>

// Problem shape (fixed by setup_inputs): B=8, Sq=Sk=1024, D=64, N_QUBITS=4.
#define B_     8
#define SQ_    1024
#define SK_    1024
#define D_     64
#define NQ_    4

// ---------------------------------------------------------------------------
// packed f32x2 helpers
// ---------------------------------------------------------------------------
__device__ __forceinline__ unsigned long long f2fma(unsigned long long a,
                                                    unsigned long long b,
                                                    unsigned long long c)
{
    unsigned long long d;
    asm("fma.rn.f32x2 %0, %1, %2, %3;" : "=l"(d) : "l"(a), "l"(b), "l"(c));
    return d;
}
__device__ __forceinline__ unsigned long long f2mul(unsigned long long a,
                                                    unsigned long long b)
{
    unsigned long long d;
    asm("mul.rn.f32x2 %0, %1, %2;" : "=l"(d) : "l"(a), "l"(b));
    return d;
}
__device__ __forceinline__ unsigned long long f2dup(float v)
{
    unsigned long long d;
    asm("mov.b64 %0, {%1, %1};" : "=l"(d) : "f"(v));
    return d;
}

#define HALF2_  0x3F0000003F000000ULL   // {0.5f, 0.5f}
#define QUART2_ 0x3E8000003E800000ULL   // {0.25f, 0.25f}
#define PI_     3.14159265358979323846f

// fast tanh: 1 - 2/(e^{2x}+1).  MUFU ex2 + rcp; saturates correctly at +-1.
__device__ __forceinline__ float fast_tanh(float x)
{
    float e = __expf(2.0f * x);
    return 1.0f - __fdividef(2.0f, e + 1.0f);
}

// Bloch-rotation columns of M = Rz(om)*Ry(th)*Rz(phi):  u = M*ex, v = M*ez
__device__ __forceinline__ void uv_cols(float phi, float th, float om,
                                        float u[3], float v[3])
{
    float sp, cp, st, ct, so, co;
    __sincosf(phi, &sp, &cp);
    __sincosf(th,  &st, &ct);
    __sincosf(om,  &so, &co);
    float ax = ct * cp, ay = sp, az = -st * cp;
    u[0] = ax * co - ay * so;
    u[1] = ax * so + ay * co;
    u[2] = az;
    v[0] = st * co;
    v[1] = st * so;
    v[2] = ct;
}

// per-row trig: t = tanh(x), (S,C) = sincos(pi t)
__device__ __forceinline__ void row_sc(float4 xv, float S[NQ_], float C[NQ_])
{
    float xs[4] = {xv.x, xv.y, xv.z, xv.w};
#pragma unroll
    for (int n = 0; n < NQ_; n++) {
        float t = fast_tanh(xs[n]);
        __sincosf(t * PI_, &S[n], &C[n]);
    }
}

// ---------------------------------------------------------------------------
// FUSED kernel, single __syncthreads, 256-q-row tile (single wave: 256 blocks)
//   out[b][q][k] = 0.5 + t0'*t1*t2*t3,  t0' = 0.25 + q0'.(G_0 k)  (q0' has
//   the global 0.5 output scale pre-folded: q0' = 0.25*(S,C)),
//   t_n = 0.5 + q.(G_n k) for n>=1 with q = 0.5*(S,C).
// prep: every thread computes q row `tid`; threads 128..255 also compute raw
// k col `tid-128`; threads 0..15 also compute the 16 Gram entries.
// main: thread owns 4 k-cols as packed f32x2 pairs (G folded once in regs),
// iterates 32 q-rows jammed 2 at a time; epilogue per chain is
// 2 f2mul + 1 f2fma (half/quarter constants folded into q scaling).
// ---------------------------------------------------------------------------
#define TQ 256
#define TK 128

__global__ __launch_bounds__(256, 3) void fused_kernel(
    float* __restrict__ out,
    const float* __restrict__ query,
    const float* __restrict__ key,
    const float* __restrict__ theta_q,
    const float* __restrict__ theta_k)
{
    __shared__ __align__(16) float  sq[TQ][8];         // scaled (S,C) q rows
    __shared__ __align__(16) float4 skv[8][TK / 4];    // SoA RAW k tile
    __shared__ __align__(8)  float2 sGd[16];           // {g,g} duplicated

    int b  = blockIdx.z;
    int q0 = blockIdx.y * TQ;
    int k0 = blockIdx.x * TK;
    int tid = threadIdx.x;

    // ---- issue row LDGs first (overlap the Gram chain) ----
    float4 xq = *(const float4*)(query + (size_t)(b * SQ_ + q0 + tid) * D_);
    bool hasK = tid >= 128;
    float4 xk;
    if (hasK)
        xk = *(const float4*)(key + (size_t)(b * SK_ + k0 + (tid - 128)) * D_);

    // ---- Gram entries (threads 0..15, redundant per block) ----
    if (tid < 16) {
        int n = tid >> 2, i = (tid >> 1) & 1, j = tid & 1;
        float uq[3], vq[3], uk[3], vk[3];
        uv_cols(theta_q[3 * n], theta_q[3 * n + 1], theta_q[3 * n + 2], uq, vq);
        uv_cols(theta_k[3 * n], theta_k[3 * n + 1], theta_k[3 * n + 2], uk, vk);
        const float* a  = i ? vq : uq;
        const float* bb = j ? vk : uk;
        float g = a[0] * bb[0] + a[1] * bb[1] + a[2] * bb[2];
        sGd[tid] = make_float2(g, g);
    }

    // ---- q row (every thread); qubit 0 pre-scaled 0.25 (output-scale fold) ----
    {
        float S[NQ_], C[NQ_];
        row_sc(xq, S, C);
        float out8[8];
#pragma unroll
        for (int n = 0; n < NQ_; n++) {
            float sc = (n == 0) ? 0.25f : 0.5f;
            out8[2 * n]     = sc * S[n];
            out8[2 * n + 1] = sc * C[n];
        }
        *(float4*)&sq[tid][0] = *(const float4*)(out8);
        *(float4*)&sq[tid][4] = *(const float4*)(out8 + 4);
    }

    // ---- raw k col (threads 128..255) ----
    if (hasK) {
        float S[NQ_], C[NQ_];
        row_sc(xk, S, C);
        int s = tid - 128;
        float* skf = (float*)skv;   // [comp][TK] floats
#pragma unroll
        for (int n = 0; n < NQ_; n++) {
            skf[(2 * n)     * TK + s] = S[n];
            skf[(2 * n + 1) * TK + s] = C[n];
        }
    }
    __syncthreads();           // sGd + both tiles ready (single barrier)

    int k4 = tid & 31;     // this thread's 4 consecutive k columns
    int qg = tid >> 5;     // q group: rows qg*32 .. qg*32+31

    // raw k tile -> registers, fold G once (16 packed ops, one-time)
    ulonglong2 kd[8];
#pragma unroll
    for (int j = 0; j < 8; j++)
        kd[j] = *(const ulonglong2*)&skv[j][k4];

#pragma unroll
    for (int n = 0; n < NQ_; n++) {
        unsigned long long g00 = *(const unsigned long long*)&sGd[n * 4 + 0];
        unsigned long long g01 = *(const unsigned long long*)&sGd[n * 4 + 1];
        unsigned long long g10 = *(const unsigned long long*)&sGd[n * 4 + 2];
        unsigned long long g11 = *(const unsigned long long*)&sGd[n * 4 + 3];
        ulonglong2 Sv = kd[2 * n], Cv = kd[2 * n + 1];
        kd[2 * n].x     = f2fma(g00, Sv.x, f2mul(g01, Cv.x));
        kd[2 * n].y     = f2fma(g00, Sv.y, f2mul(g01, Cv.y));
        kd[2 * n + 1].x = f2fma(g10, Sv.x, f2mul(g11, Cv.x));
        kd[2 * n + 1].y = f2fma(g10, Sv.y, f2mul(g11, Cv.y));
    }

    float* obase = out + ((size_t)(b * SQ_ + q0 + qg * 32) * SK_) + k0 + k4 * 4;

#pragma unroll
    for (int rr = 0; rr < 16; rr++) {
        int ra = qg * 32 + 2 * rr;

        // two rows' q vectors (4 warp-uniform LDS.128)
        float4 a0 = *(const float4*)&sq[ra][0];
        float4 a1 = *(const float4*)&sq[ra][4];
        float4 b0 = *(const float4*)&sq[ra + 1][0];
        float4 b1 = *(const float4*)&sq[ra + 1][4];

        unsigned long long qa[8], qb[8];
        qa[0] = f2dup(a0.x); qa[1] = f2dup(a0.y);
        qa[2] = f2dup(a0.z); qa[3] = f2dup(a0.w);
        qa[4] = f2dup(a1.x); qa[5] = f2dup(a1.y);
        qa[6] = f2dup(a1.z); qa[7] = f2dup(a1.w);
        qb[0] = f2dup(b0.x); qb[1] = f2dup(b0.y);
        qb[2] = f2dup(b0.z); qb[3] = f2dup(b0.w);
        qb[4] = f2dup(b1.x); qb[5] = f2dup(b1.y);
        qb[6] = f2dup(b1.z); qb[7] = f2dup(b1.w);

        unsigned long long ta0[NQ_], ta1[NQ_], tb0[NQ_], tb1[NQ_];
#pragma unroll
        for (int n = 0; n < NQ_; n++) {
            unsigned long long c = (n == 0) ? QUART2_ : HALF2_;
            ta0[n] = f2fma(qa[2 * n], kd[2 * n].x,
                     f2fma(qa[2 * n + 1], kd[2 * n + 1].x, c));
            ta1[n] = f2fma(qa[2 * n], kd[2 * n].y,
                     f2fma(qa[2 * n + 1], kd[2 * n + 1].y, c));
            tb0[n] = f2fma(qb[2 * n], kd[2 * n].x,
                     f2fma(qb[2 * n + 1], kd[2 * n + 1].x, c));
            tb1[n] = f2fma(qb[2 * n], kd[2 * n].y,
                     f2fma(qb[2 * n + 1], kd[2 * n + 1].y, c));
        }
        // out = 0.5 + (t0'*t1)*(t2*t3)   (2 muls + 1 fma per chain)
        unsigned long long pa0 = f2fma(f2mul(ta0[0], ta0[1]),
                                       f2mul(ta0[2], ta0[3]), HALF2_);
        unsigned long long pa1 = f2fma(f2mul(ta1[0], ta1[1]),
                                       f2mul(ta1[2], ta1[3]), HALF2_);
        unsigned long long pb0 = f2fma(f2mul(tb0[0], tb0[1]),
                                       f2mul(tb0[2], tb0[3]), HALF2_);
        unsigned long long pb1 = f2fma(f2mul(tb1[0], tb1[1]),
                                       f2mul(tb1[2], tb1[3]), HALF2_);

        float* oa = obase + (size_t)(2 * rr) * SK_;
        asm volatile("st.global.v2.b64 [%0], {%1, %2};"
                     :: "l"(oa), "l"(pa0), "l"(pa1) : "memory");
        asm volatile("st.global.v2.b64 [%0], {%1, %2};"
                     :: "l"(oa + SK_), "l"(pb0), "l"(pb1) : "memory");
    }
}

extern "C" void kernel_launch(void* const* d_in, const int* in_sizes, int n_in,
                              void* d_out, int out_size)
{
    const float* query   = (const float*)d_in[0];
    const float* key     = (const float*)d_in[1];
    const float* theta_q = (const float*)d_in[2];
    const float* theta_k = (const float*)d_in[3];
    float* out = (float*)d_out;

    dim3 grid(SK_ / TK, SQ_ / TQ, B_);
    fused_kernel<<<grid, 256>>>(out, query, key, theta_q, theta_k);
}